// round 1
// baseline (speedup 1.0000x reference)
#include <cuda_runtime.h>
#include <math.h>
#include <stdint.h>

// Problem constants
#define B_   4
#define S_   1024
#define E_   256
#define H_   32
#define DK_  8
#define NQ_  8
#define FF_  1024
#define M_   (B_ * S_)   // 4096

// ---------------- scratch (device globals; no runtime allocation) ----------
__device__ __align__(16) float g_qout[M_ * E_];        // cos(x + theta)
__device__ __align__(16) float g_qkv[M_ * 3 * E_];     // packed qkv
__device__ __align__(16) float g_ctx[M_ * E_];         // attention context
__device__ __align__(16) float g_Wf[E_ * E_];          // folded w_comb@w_out
__device__ __align__(16) float g_bf[E_];               // folded bias
__device__ __align__(16) float g_tmp[M_ * E_];         // attn_out / ffn_out
__device__ __align__(16) float g_h[M_ * E_];           // post-LN1 hidden
__device__ __align__(16) float g_qf[M_ * NQ_];         // quantum ffn features
__device__ __align__(16) float g_hidden[M_ * FF_];     // relu hidden

// ---------------- elementwise: q_out = cos(x + theta[e % 8]) ----------------
__global__ __launch_bounds__(256) void cos_encode_kernel(
    const float* __restrict__ x, const float* __restrict__ theta)
{
    int i = blockIdx.x * 256 + threadIdx.x;
    g_qout[i] = cosf(x[i] + theta[i & 7]);
}

// ---------------- fold: Wf = w_comb @ w_out, bf = w_comb@b_out + b_comb -----
__global__ __launch_bounds__(256) void fold_w_kernel(
    const float* __restrict__ w_comb, const float* __restrict__ w_out,
    const float* __restrict__ b_out, const float* __restrict__ b_comb)
{
    int i = blockIdx.x;    // output row of Wf
    int j = threadIdx.x;   // output col of Wf
    float s = 0.f;
    #pragma unroll 8
    for (int k = 0; k < E_; k++)
        s = fmaf(w_comb[i * E_ + k], w_out[k * E_ + j], s);
    g_Wf[i * E_ + j] = s;

    __shared__ float red[256];
    red[j] = w_comb[i * E_ + j] * b_out[j];
    __syncthreads();
    #pragma unroll
    for (int off = 128; off > 0; off >>= 1) {
        if (j < off) red[j] += red[j + off];
        __syncthreads();
    }
    if (j == 0) g_bf[i] = red[0] + b_comb[i];
}

// ---------------- generic SGEMM: C[M,N] = A[M,K] @ Bw[N,K]^T + bias ---------
// BM=BN=64, BK=16, 256 threads, 4x4 microtile. M%64==0, N%64==0, K%16==0.
__global__ __launch_bounds__(256) void sgemm_kernel(
    const float* __restrict__ A, const float* __restrict__ Bw,
    const float* __restrict__ bias, float* __restrict__ C,
    int M, int N, int K, int relu)
{
    __shared__ float As[16][68];
    __shared__ float Bs[16][68];

    int tid = threadIdx.x;
    int bm = blockIdx.y * 64;
    int bn = blockIdx.x * 64;
    int tx = tid & 15;        // 0..15 (n)
    int ty = tid >> 4;        // 0..15 (m)
    int lr = tid >> 2;        // 0..63 load row
    int lc = (tid & 3) << 2;  // 0,4,8,12 load col

    float acc[4][4] = {};

    for (int k0 = 0; k0 < K; k0 += 16) {
        float4 av = *(const float4*)(A  + (size_t)(bm + lr) * K + k0 + lc);
        float4 bv = *(const float4*)(Bw + (size_t)(bn + lr) * K + k0 + lc);
        As[lc + 0][lr] = av.x; As[lc + 1][lr] = av.y;
        As[lc + 2][lr] = av.z; As[lc + 3][lr] = av.w;
        Bs[lc + 0][lr] = bv.x; Bs[lc + 1][lr] = bv.y;
        Bs[lc + 2][lr] = bv.z; Bs[lc + 3][lr] = bv.w;
        __syncthreads();

        #pragma unroll
        for (int kk = 0; kk < 16; kk++) {
            float4 a = *(const float4*)&As[kk][ty * 4];
            float4 b = *(const float4*)&Bs[kk][tx * 4];
            float ax[4] = {a.x, a.y, a.z, a.w};
            float bx[4] = {b.x, b.y, b.z, b.w};
            #pragma unroll
            for (int i = 0; i < 4; i++)
                #pragma unroll
                for (int j = 0; j < 4; j++)
                    acc[i][j] = fmaf(ax[i], bx[j], acc[i][j]);
        }
        __syncthreads();
    }

    int col = bn + tx * 4;
    float4 bb = *(const float4*)(bias + col);
    #pragma unroll
    for (int i = 0; i < 4; i++) {
        int row = bm + ty * 4 + i;
        float4 v;
        v.x = acc[i][0] + bb.x;
        v.y = acc[i][1] + bb.y;
        v.z = acc[i][2] + bb.z;
        v.w = acc[i][3] + bb.w;
        if (relu) {
            v.x = fmaxf(v.x, 0.f); v.y = fmaxf(v.y, 0.f);
            v.z = fmaxf(v.z, 0.f); v.w = fmaxf(v.w, 0.f);
        }
        *(float4*)(C + (size_t)row * N + col) = v;
    }
}

// ---------------- attention: one CTA per (b,h), K/V resident in SMEM --------
__global__ __launch_bounds__(512) void attn_kernel()
{
    extern __shared__ float sm[];
    float* Ks = sm;            // 1024 x 8
    float* Vs = sm + S_ * DK_; // 1024 x 8

    int bh = blockIdx.x;
    int b  = bh >> 5;
    int h  = bh & 31;
    const float* base = g_qkv + (size_t)b * S_ * (3 * E_) + h * DK_;

    // stage K and V
    for (int s = threadIdx.x; s < S_; s += 512) {
        const float4* kp = (const float4*)(base + (size_t)s * (3 * E_) + E_);
        const float4* vp = (const float4*)(base + (size_t)s * (3 * E_) + 2 * E_);
        float4 k0 = kp[0], k1 = kp[1];
        float4 v0 = vp[0], v1 = vp[1];
        ((float4*)Ks)[2 * s]     = k0;
        ((float4*)Ks)[2 * s + 1] = k1;
        ((float4*)Vs)[2 * s]     = v0;
        ((float4*)Vs)[2 * s + 1] = v1;
    }
    __syncthreads();

    const float scale = 0.35355339059327373f; // 1/sqrt(8)
    int qi0 = threadIdx.x;
    int qi1 = threadIdx.x + 512;

    float q0[8], q1[8];
    {
        const float4* qp0 = (const float4*)(base + (size_t)qi0 * (3 * E_));
        const float4* qp1 = (const float4*)(base + (size_t)qi1 * (3 * E_));
        float4 t0 = qp0[0], t1 = qp0[1];
        float4 u0 = qp1[0], u1 = qp1[1];
        q0[0] = t0.x * scale; q0[1] = t0.y * scale; q0[2] = t0.z * scale; q0[3] = t0.w * scale;
        q0[4] = t1.x * scale; q0[5] = t1.y * scale; q0[6] = t1.z * scale; q0[7] = t1.w * scale;
        q1[0] = u0.x * scale; q1[1] = u0.y * scale; q1[2] = u0.z * scale; q1[3] = u0.w * scale;
        q1[4] = u1.x * scale; q1[5] = u1.y * scale; q1[6] = u1.z * scale; q1[7] = u1.w * scale;
    }

    float acc0[8] = {}, acc1[8] = {};
    float m0 = -1e30f, m1 = -1e30f, l0 = 0.f, l1 = 0.f;

    for (int s = 0; s < S_; s++) {
        float4 ka = ((const float4*)Ks)[2 * s];
        float4 kb = ((const float4*)Ks)[2 * s + 1];
        float d0 = q0[0]*ka.x + q0[1]*ka.y + q0[2]*ka.z + q0[3]*ka.w
                 + q0[4]*kb.x + q0[5]*kb.y + q0[6]*kb.z + q0[7]*kb.w;
        float d1 = q1[0]*ka.x + q1[1]*ka.y + q1[2]*ka.z + q1[3]*ka.w
                 + q1[4]*kb.x + q1[5]*kb.y + q1[6]*kb.z + q1[7]*kb.w;
        float4 va = ((const float4*)Vs)[2 * s];
        float4 vb = ((const float4*)Vs)[2 * s + 1];

        if (d0 > m0) {  // rare rescale
            float c = __expf(m0 - d0);
            l0 *= c;
            #pragma unroll
            for (int i = 0; i < 8; i++) acc0[i] *= c;
            m0 = d0;
        }
        float p0 = __expf(d0 - m0);
        l0 += p0;
        acc0[0] = fmaf(p0, va.x, acc0[0]); acc0[1] = fmaf(p0, va.y, acc0[1]);
        acc0[2] = fmaf(p0, va.z, acc0[2]); acc0[3] = fmaf(p0, va.w, acc0[3]);
        acc0[4] = fmaf(p0, vb.x, acc0[4]); acc0[5] = fmaf(p0, vb.y, acc0[5]);
        acc0[6] = fmaf(p0, vb.z, acc0[6]); acc0[7] = fmaf(p0, vb.w, acc0[7]);

        if (d1 > m1) {
            float c = __expf(m1 - d1);
            l1 *= c;
            #pragma unroll
            for (int i = 0; i < 8; i++) acc1[i] *= c;
            m1 = d1;
        }
        float p1 = __expf(d1 - m1);
        l1 += p1;
        acc1[0] = fmaf(p1, va.x, acc1[0]); acc1[1] = fmaf(p1, va.y, acc1[1]);
        acc1[2] = fmaf(p1, va.z, acc1[2]); acc1[3] = fmaf(p1, va.w, acc1[3]);
        acc1[4] = fmaf(p1, vb.x, acc1[4]); acc1[5] = fmaf(p1, vb.y, acc1[5]);
        acc1[6] = fmaf(p1, vb.z, acc1[6]); acc1[7] = fmaf(p1, vb.w, acc1[7]);
    }

    float r0 = 1.f / l0;
    float r1 = 1.f / l1;
    size_t o0 = ((size_t)b * S_ + qi0) * E_ + h * DK_;
    size_t o1 = ((size_t)b * S_ + qi1) * E_ + h * DK_;
    float4 w;
    w.x = acc0[0]*r0; w.y = acc0[1]*r0; w.z = acc0[2]*r0; w.w = acc0[3]*r0;
    *(float4*)(g_ctx + o0) = w;
    w.x = acc0[4]*r0; w.y = acc0[5]*r0; w.z = acc0[6]*r0; w.w = acc0[7]*r0;
    *(float4*)(g_ctx + o0 + 4) = w;
    w.x = acc1[0]*r1; w.y = acc1[1]*r1; w.z = acc1[2]*r1; w.w = acc1[3]*r1;
    *(float4*)(g_ctx + o1) = w;
    w.x = acc1[4]*r1; w.y = acc1[5]*r1; w.z = acc1[6]*r1; w.w = acc1[7]*r1;
    *(float4*)(g_ctx + o1 + 4) = w;
}

// ---------------- layernorm: out = LN(a + b) * g + beta  (warp per row) -----
__global__ __launch_bounds__(256) void ln_kernel(
    const float* __restrict__ a, const float* __restrict__ bsrc,
    const float* __restrict__ g, const float* __restrict__ beta,
    float* __restrict__ out)
{
    int row  = (blockIdx.x * 256 + threadIdx.x) >> 5;
    int lane = threadIdx.x & 31;
    size_t off = (size_t)row * E_ + lane * 8;

    const float4* ap = (const float4*)(a + off);
    const float4* bp = (const float4*)(bsrc + off);
    float4 a0 = ap[0], a1 = ap[1], b0 = bp[0], b1 = bp[1];
    float v[8];
    v[0] = a0.x + b0.x; v[1] = a0.y + b0.y; v[2] = a0.z + b0.z; v[3] = a0.w + b0.w;
    v[4] = a1.x + b1.x; v[5] = a1.y + b1.y; v[6] = a1.z + b1.z; v[7] = a1.w + b1.w;

    float s = 0.f, ss = 0.f;
    #pragma unroll
    for (int i = 0; i < 8; i++) { s += v[i]; ss = fmaf(v[i], v[i], ss); }
    #pragma unroll
    for (int o = 16; o > 0; o >>= 1) {
        s  += __shfl_xor_sync(0xFFFFFFFFu, s,  o);
        ss += __shfl_xor_sync(0xFFFFFFFFu, ss, o);
    }
    float mu  = s * (1.f / E_);
    float var = ss * (1.f / E_) - mu * mu;
    float rs  = rsqrtf(var + 1e-5f);

    const float4* gp  = (const float4*)(g    + lane * 8);
    const float4* bep = (const float4*)(beta + lane * 8);
    float4 g0 = gp[0], g1v = gp[1], e0 = bep[0], e1 = bep[1];

    float4 w;
    w.x = (v[0]-mu)*rs*g0.x + e0.x; w.y = (v[1]-mu)*rs*g0.y + e0.y;
    w.z = (v[2]-mu)*rs*g0.z + e0.z; w.w = (v[3]-mu)*rs*g0.w + e0.w;
    *(float4*)(out + off) = w;
    w.x = (v[4]-mu)*rs*g1v.x + e1.x; w.y = (v[5]-mu)*rs*g1v.y + e1.y;
    w.z = (v[6]-mu)*rs*g1v.z + e1.z; w.w = (v[7]-mu)*rs*g1v.w + e1.w;
    *(float4*)(out + off + 4) = w;
}

// ---------------- qf = cos(theta_ffn) * cos(h @ w_ip^T + b_ip) --------------
__global__ __launch_bounds__(256) void qf_kernel(
    const float* __restrict__ w_ip, const float* __restrict__ b_ip,
    const float* __restrict__ theta_ffn)
{
    int m    = blockIdx.x;
    int j    = threadIdx.x >> 5;   // 0..7
    int lane = threadIdx.x & 31;
    const float* hr = g_h + (size_t)m * E_;
    const float* wr = w_ip + (size_t)j * E_;
    float s = 0.f;
    #pragma unroll
    for (int e = 0; e < E_; e += 32)
        s = fmaf(hr[e + lane], wr[e + lane], s);
    #pragma unroll
    for (int o = 16; o > 0; o >>= 1)
        s += __shfl_xor_sync(0xFFFFFFFFu, s, o);
    if (lane == 0)
        g_qf[m * NQ_ + j] = cosf(theta_ffn[j]) * cosf(s + b_ip[j]);
}

// ---------------- hidden = relu(qf @ w1^T + b1)   (K=8) ---------------------
__global__ __launch_bounds__(256) void hidden_kernel(
    const float* __restrict__ w1, const float* __restrict__ b1)
{
    int m = blockIdx.x >> 2;
    int f = ((blockIdx.x & 3) << 8) + threadIdx.x;
    const float* qr = g_qf + (size_t)m * NQ_;
    const float* wr = w1 + (size_t)f * NQ_;
    float s = b1[f];
    #pragma unroll
    for (int j = 0; j < NQ_; j++)
        s = fmaf(qr[j], wr[j], s);
    g_hidden[(size_t)m * FF_ + f] = fmaxf(s, 0.f);
}

// ---------------- launch ----------------------------------------------------
extern "C" void kernel_launch(void* const* d_in, const int* in_sizes, int n_in,
                              void* d_out, int out_size)
{
    (void)in_sizes; (void)n_in; (void)out_size;

    const float* x          = (const float*)d_in[0];
    const float* theta_attn = (const float*)d_in[1];
    const float* w_in       = (const float*)d_in[2];
    const float* b_in       = (const float*)d_in[3];
    const float* w_out      = (const float*)d_in[4];
    const float* b_out      = (const float*)d_in[5];
    const float* w_comb     = (const float*)d_in[6];
    const float* b_comb     = (const float*)d_in[7];
    const float* g1         = (const float*)d_in[8];
    const float* be1        = (const float*)d_in[9];
    const float* g2         = (const float*)d_in[10];
    const float* be2        = (const float*)d_in[11];
    const float* w_ip       = (const float*)d_in[12];
    const float* b_ip       = (const float*)d_in[13];
    const float* theta_ffn  = (const float*)d_in[14];
    const float* w1         = (const float*)d_in[15];
    const float* b1         = (const float*)d_in[16];
    const float* w2         = (const float*)d_in[17];
    const float* b2         = (const float*)d_in[18];
    float* out = (float*)d_out;

    // scratch pointers (device globals -> host-usable addresses)
    float *p_qout, *p_qkv, *p_ctx, *p_Wf, *p_bf, *p_tmp, *p_h, *p_hidden;
    cudaGetSymbolAddress((void**)&p_qout,   g_qout);
    cudaGetSymbolAddress((void**)&p_qkv,    g_qkv);
    cudaGetSymbolAddress((void**)&p_ctx,    g_ctx);
    cudaGetSymbolAddress((void**)&p_Wf,     g_Wf);
    cudaGetSymbolAddress((void**)&p_bf,     g_bf);
    cudaGetSymbolAddress((void**)&p_tmp,    g_tmp);
    cudaGetSymbolAddress((void**)&p_h,      g_h);
    cudaGetSymbolAddress((void**)&p_hidden, g_hidden);

    cudaFuncSetAttribute(attn_kernel,
                         cudaFuncAttributeMaxDynamicSharedMemorySize,
                         2 * S_ * DK_ * sizeof(float));

    // 1. q_out = cos(x + theta)
    cos_encode_kernel<<<(M_ * E_) / 256, 256>>>(x, theta_attn);

    // 2. fold w_comb @ w_out (independent; small)
    fold_w_kernel<<<E_, 256>>>(w_comb, w_out, b_out, b_comb);

    // 3. qkv = q_out @ w_in^T + b_in      [4096 x 768]
    {
        dim3 grid((3 * E_) / 64, M_ / 64);
        sgemm_kernel<<<grid, 256>>>(p_qout, w_in, b_in, p_qkv,
                                    M_, 3 * E_, E_, 0);
    }

    // 4. attention -> ctx                 [4096 x 256]
    attn_kernel<<<B_ * H_, 512, 2 * S_ * DK_ * sizeof(float)>>>();

    // 5. attn_out = ctx @ Wf^T + bf       [4096 x 256]
    {
        dim3 grid(E_ / 64, M_ / 64);
        sgemm_kernel<<<grid, 256>>>(p_ctx, p_Wf, p_bf, p_tmp,
                                    M_, E_, E_, 0);
    }

    // 6. h = LN(x + attn_out) * g1 + be1
    ln_kernel<<<M_ / 8, 256>>>(x, p_tmp, g1, be1, p_h);

    // 7. qf = cos(theta_ffn) * cos(h @ w_ip^T + b_ip)
    qf_kernel<<<M_, 256>>>(w_ip, b_ip, theta_ffn);

    // 8. hidden = relu(qf @ w1^T + b1)    [4096 x 1024]
    hidden_kernel<<<M_ * 4, 256>>>(w1, b1);

    // 9. ffn_out = hidden @ w2^T + b2     [4096 x 256]
    {
        dim3 grid(E_ / 64, M_ / 64);
        sgemm_kernel<<<grid, 256>>>(p_hidden, w2, b2, p_tmp,
                                    M_, E_, FF_, 0);
    }

    // 10. out = LN(h + ffn_out) * g2 + be2
    ln_kernel<<<M_ / 8, 256>>>(p_h, p_tmp, g2, be2, out);
}

// round 2
// speedup vs baseline: 1.0877x; 1.0877x over previous
#include <cuda_runtime.h>
#include <math.h>
#include <stdint.h>

// Problem constants
#define B_   4
#define S_   1024
#define E_   256
#define H_   32
#define DK_  8
#define NQ_  8
#define FF_  1024
#define M_   (B_ * S_)   // 4096

typedef unsigned long long ULL;

// ---------------- f32x2 packed math helpers (PTX-only on sm_103a) ----------
__device__ __forceinline__ ULL fma2(ULL a, ULL b, ULL c) {
    ULL d; asm("fma.rn.f32x2 %0, %1, %2, %3;" : "=l"(d) : "l"(a), "l"(b), "l"(c)); return d;
}
__device__ __forceinline__ ULL mul2(ULL a, ULL b) {
    ULL d; asm("mul.rn.f32x2 %0, %1, %2;" : "=l"(d) : "l"(a), "l"(b)); return d;
}
__device__ __forceinline__ ULL add2(ULL a, ULL b) {
    ULL d; asm("add.rn.f32x2 %0, %1, %2;" : "=l"(d) : "l"(a), "l"(b)); return d;
}
__device__ __forceinline__ ULL pk(float lo, float hi) {
    ULL r; asm("mov.b64 %0, {%1, %2};" : "=l"(r) : "f"(lo), "f"(hi)); return r;
}
__device__ __forceinline__ void unpk(ULL v, float& lo, float& hi) {
    asm("mov.b64 {%0, %1}, %2;" : "=f"(lo), "=f"(hi) : "l"(v));
}
__device__ __forceinline__ float ex2f_(float x) {
    float y; asm("ex2.approx.f32 %0, %1;" : "=f"(y) : "f"(x)); return y;
}

// ---------------- scratch (device globals; no runtime allocation) ----------
__device__ __align__(16) float g_qout[M_ * E_];
__device__ __align__(16) float g_qkv[M_ * 3 * E_];
__device__ __align__(16) float g_ctx[M_ * E_];
__device__ __align__(16) float g_Wf[E_ * E_];
__device__ __align__(16) float g_bf[E_];
__device__ __align__(16) float g_tmp[M_ * E_];
__device__ __align__(16) float g_h[M_ * E_];
__device__ __align__(16) float g_qf[M_ * NQ_];
__device__ __align__(16) float g_hidden[M_ * FF_];

// ---------------- q_out = cos(x + theta[e % 8]), float4 --------------------
__global__ __launch_bounds__(256) void cos_encode_kernel(
    const float* __restrict__ x, const float* __restrict__ theta)
{
    int i = (blockIdx.x * 256 + threadIdx.x) * 4;
    float4 v = *(const float4*)(x + i);
    int j = i & 7;  // 0 or 4
    v.x = __cosf(v.x + theta[j + 0]);
    v.y = __cosf(v.y + theta[j + 1]);
    v.z = __cosf(v.z + theta[j + 2]);
    v.w = __cosf(v.w + theta[j + 3]);
    *(float4*)(g_qout + i) = v;
}

// ---------------- fold: Wf = w_comb @ w_out, bf = w_comb@b_out + b_comb -----
__global__ __launch_bounds__(256) void fold_w_kernel(
    const float* __restrict__ w_comb, const float* __restrict__ w_out,
    const float* __restrict__ b_out, const float* __restrict__ b_comb)
{
    int i = blockIdx.x;
    int j = threadIdx.x;
    float s = 0.f;
    #pragma unroll 8
    for (int k = 0; k < E_; k++)
        s = fmaf(w_comb[i * E_ + k], w_out[k * E_ + j], s);
    g_Wf[i * E_ + j] = s;

    __shared__ float red[256];
    red[j] = w_comb[i * E_ + j] * b_out[j];
    __syncthreads();
    #pragma unroll
    for (int off = 128; off > 0; off >>= 1) {
        if (j < off) red[j] += red[j + off];
        __syncthreads();
    }
    if (j == 0) g_bf[i] = red[0] + b_comb[i];
}

// ---------------- f32x2 SGEMM: C[M,N] = A[M,K] @ Bw[N,K]^T + bias ----------
// BM=128, BN=64, BK=16, 256 threads, 8x4 microtile with m-row pairs packed.
// Requires M%128==0, N%64==0, K%16==0.
__global__ __launch_bounds__(256) void sgemm2_kernel(
    const float* __restrict__ A, const float* __restrict__ Bw,
    const float* __restrict__ bias, float* __restrict__ C,
    int M, int N, int K, int relu)
{
    __shared__ float As[16][132];   // [k][m], row stride 132 (528B = 33*16B)
    __shared__ float Bs[16][68];    // [k][n]

    int tid = threadIdx.x;
    int bm = blockIdx.y * 128;
    int bn = blockIdx.x * 64;
    int ty = tid >> 4;              // 0..15 -> 8 m-rows
    int tx = tid & 15;              // 0..15 -> 4 n-cols

    int alr = tid >> 1;             // 0..127 (A tile row)
    int alc = (tid & 1) * 8;        // 0 or 8 (A tile k-offset)
    int blr = tid >> 2;             // 0..63  (B tile row)
    int blc = (tid & 3) * 4;        // 0,4,8,12

    const float* Aptr = A  + (size_t)(bm + alr) * K + alc;
    const float* Bptr = Bw + (size_t)(bn + blr) * K + blc;

    float4 a0 = *(const float4*)(Aptr);
    float4 a1 = *(const float4*)(Aptr + 4);
    float4 b0 = *(const float4*)(Bptr);

    ULL acc[4][4];
    #pragma unroll
    for (int r = 0; r < 4; r++)
        #pragma unroll
        for (int j = 0; j < 4; j++) acc[r][j] = 0ULL;

    for (int k0 = 0; ; k0 += 16) {
        // commit staged registers to smem (transposed)
        As[alc + 0][alr] = a0.x; As[alc + 1][alr] = a0.y;
        As[alc + 2][alr] = a0.z; As[alc + 3][alr] = a0.w;
        As[alc + 4][alr] = a1.x; As[alc + 5][alr] = a1.y;
        As[alc + 6][alr] = a1.z; As[alc + 7][alr] = a1.w;
        Bs[blc + 0][blr] = b0.x; Bs[blc + 1][blr] = b0.y;
        Bs[blc + 2][blr] = b0.z; Bs[blc + 3][blr] = b0.w;
        __syncthreads();

        bool last = (k0 + 16 >= K);
        if (!last) {  // prefetch next tile; LDG latency hides under compute
            Aptr += 16; Bptr += 16;
            a0 = *(const float4*)(Aptr);
            a1 = *(const float4*)(Aptr + 4);
            b0 = *(const float4*)(Bptr);
        }

        #pragma unroll
        for (int kk = 0; kk < 16; kk++) {
            ulonglong2 am0 = *(const ulonglong2*)&As[kk][ty * 8];
            ulonglong2 am1 = *(const ulonglong2*)&As[kk][ty * 8 + 4];
            float4 b4 = *(const float4*)&Bs[kk][tx * 4];
            ULL bb0 = pk(b4.x, b4.x), bb1 = pk(b4.y, b4.y);
            ULL bb2 = pk(b4.z, b4.z), bb3 = pk(b4.w, b4.w);
            ULL am[4] = {am0.x, am0.y, am1.x, am1.y};
            #pragma unroll
            for (int r = 0; r < 4; r++) {
                acc[r][0] = fma2(am[r], bb0, acc[r][0]);
                acc[r][1] = fma2(am[r], bb1, acc[r][1]);
                acc[r][2] = fma2(am[r], bb2, acc[r][2]);
                acc[r][3] = fma2(am[r], bb3, acc[r][3]);
            }
        }
        if (last) break;
        __syncthreads();
    }

    int col = bn + tx * 4;
    float4 bb = *(const float4*)(bias + col);
    #pragma unroll
    for (int r = 0; r < 4; r++) {
        float lo0, hi0, lo1, hi1, lo2v, hi2, lo3, hi3;
        unpk(acc[r][0], lo0, hi0);
        unpk(acc[r][1], lo1, hi1);
        unpk(acc[r][2], lo2v, hi2);
        unpk(acc[r][3], lo3, hi3);
        int row0 = bm + ty * 8 + 2 * r;
        float4 v;
        v.x = lo0 + bb.x; v.y = lo1 + bb.y; v.z = lo2v + bb.z; v.w = lo3 + bb.w;
        if (relu) { v.x = fmaxf(v.x, 0.f); v.y = fmaxf(v.y, 0.f);
                    v.z = fmaxf(v.z, 0.f); v.w = fmaxf(v.w, 0.f); }
        *(float4*)(C + (size_t)row0 * N + col) = v;
        v.x = hi0 + bb.x; v.y = hi1 + bb.y; v.z = hi2 + bb.z; v.w = hi3 + bb.w;
        if (relu) { v.x = fmaxf(v.x, 0.f); v.y = fmaxf(v.y, 0.f);
                    v.z = fmaxf(v.z, 0.f); v.w = fmaxf(v.w, 0.f); }
        *(float4*)(C + (size_t)(row0 + 1) * N + col) = v;
    }
}

// ---------------- attention: grid (2, B*H), 256 threads, f32x2 inner loop ---
// Each CTA handles 512 queries of one (b,h); 2 queries per thread.
// Q is pre-scaled by (1/sqrt(dk))*log2(e) so softmax needs only ex2.approx.
__global__ __launch_bounds__(256) void attn_kernel()
{
    extern __shared__ float sm[];
    float* Ks = sm;            // 1024 x 8
    float* Vs = sm + S_ * DK_;

    int bh   = blockIdx.y;
    int half = blockIdx.x;
    int b = bh >> 5;
    int h = bh & 31;
    const float* base = g_qkv + (size_t)b * S_ * (3 * E_) + h * DK_;

    // stage K and V (both halves stage the same data; L2-resident)
    for (int s = threadIdx.x; s < S_; s += 256) {
        const float4* kp = (const float4*)(base + (size_t)s * (3 * E_) + E_);
        const float4* vp = (const float4*)(base + (size_t)s * (3 * E_) + 2 * E_);
        float4 k0 = kp[0], k1 = kp[1];
        float4 v0 = vp[0], v1 = vp[1];
        ((float4*)Ks)[2 * s]     = k0;
        ((float4*)Ks)[2 * s + 1] = k1;
        ((float4*)Vs)[2 * s]     = v0;
        ((float4*)Vs)[2 * s + 1] = v1;
    }
    __syncthreads();

    const float qscale = 0.35355339059327373f * 1.4426950408889634f; // 1/sqrt(8)*log2e
    int qi0 = half * 512 + threadIdx.x;
    int qi1 = qi0 + 256;

    // q components paired: qp[c] = (q[2c], q[2c+1])
    ULL qp0[4], qp1[4];
    {
        const float4* p0 = (const float4*)(base + (size_t)qi0 * (3 * E_));
        const float4* p1 = (const float4*)(base + (size_t)qi1 * (3 * E_));
        float4 t0 = p0[0], t1 = p0[1], u0 = p1[0], u1 = p1[1];
        qp0[0] = pk(t0.x * qscale, t0.y * qscale);
        qp0[1] = pk(t0.z * qscale, t0.w * qscale);
        qp0[2] = pk(t1.x * qscale, t1.y * qscale);
        qp0[3] = pk(t1.z * qscale, t1.w * qscale);
        qp1[0] = pk(u0.x * qscale, u0.y * qscale);
        qp1[1] = pk(u0.z * qscale, u0.w * qscale);
        qp1[2] = pk(u1.x * qscale, u1.y * qscale);
        qp1[3] = pk(u1.z * qscale, u1.w * qscale);
    }

    ULL acc0[4], acc1[4];
    #pragma unroll
    for (int j = 0; j < 4; j++) { acc0[j] = 0ULL; acc1[j] = 0ULL; }
    float m0 = -1e30f, m1 = -1e30f, l0 = 0.f, l1 = 0.f;

    const ulonglong2* K2 = (const ulonglong2*)Ks;
    const ulonglong2* V2 = (const ulonglong2*)Vs;

    #pragma unroll 2
    for (int s = 0; s < S_; s++) {
        ulonglong2 ka = K2[2 * s];
        ulonglong2 kb = K2[2 * s + 1];
        // packed dot products (scores already in log2 domain)
        ULL t0 = mul2(qp0[0], ka.x);
        t0 = fma2(qp0[1], ka.y, t0);
        t0 = fma2(qp0[2], kb.x, t0);
        t0 = fma2(qp0[3], kb.y, t0);
        ULL t1 = mul2(qp1[0], ka.x);
        t1 = fma2(qp1[1], ka.y, t1);
        t1 = fma2(qp1[2], kb.x, t1);
        t1 = fma2(qp1[3], kb.y, t1);
        float d0, d1, e0, e1;
        unpk(t0, d0, e0); d0 += e0;
        unpk(t1, d1, e1); d1 += e1;

        ulonglong2 va = V2[2 * s];
        ulonglong2 vb = V2[2 * s + 1];

        if (d0 > m0) {                 // rare rescale
            float c = ex2f_(m0 - d0);
            l0 *= c;
            ULL cp = pk(c, c);
            #pragma unroll
            for (int j = 0; j < 4; j++) acc0[j] = mul2(acc0[j], cp);
            m0 = d0;
        }
        float p0 = ex2f_(d0 - m0);
        l0 += p0;
        ULL pb0 = pk(p0, p0);
        acc0[0] = fma2(pb0, va.x, acc0[0]);
        acc0[1] = fma2(pb0, va.y, acc0[1]);
        acc0[2] = fma2(pb0, vb.x, acc0[2]);
        acc0[3] = fma2(pb0, vb.y, acc0[3]);

        if (d1 > m1) {
            float c = ex2f_(m1 - d1);
            l1 *= c;
            ULL cp = pk(c, c);
            #pragma unroll
            for (int j = 0; j < 4; j++) acc1[j] = mul2(acc1[j], cp);
            m1 = d1;
        }
        float p1 = ex2f_(d1 - m1);
        l1 += p1;
        ULL pb1 = pk(p1, p1);
        acc1[0] = fma2(pb1, va.x, acc1[0]);
        acc1[1] = fma2(pb1, va.y, acc1[1]);
        acc1[2] = fma2(pb1, vb.x, acc1[2]);
        acc1[3] = fma2(pb1, vb.y, acc1[3]);
    }

    float r0 = 1.f / l0;
    float r1 = 1.f / l1;
    ULL rp0 = pk(r0, r0), rp1 = pk(r1, r1);
    size_t o0 = ((size_t)b * S_ + qi0) * E_ + h * DK_;
    size_t o1 = ((size_t)b * S_ + qi1) * E_ + h * DK_;
    ulonglong2 w;
    w.x = mul2(acc0[0], rp0); w.y = mul2(acc0[1], rp0);
    *(ulonglong2*)(g_ctx + o0) = w;
    w.x = mul2(acc0[2], rp0); w.y = mul2(acc0[3], rp0);
    *(ulonglong2*)(g_ctx + o0 + 4) = w;
    w.x = mul2(acc1[0], rp1); w.y = mul2(acc1[1], rp1);
    *(ulonglong2*)(g_ctx + o1) = w;
    w.x = mul2(acc1[2], rp1); w.y = mul2(acc1[3], rp1);
    *(ulonglong2*)(g_ctx + o1 + 4) = w;
}

// ---------------- layernorm: out = LN(a + b) * g + beta  (warp per row) -----
__global__ __launch_bounds__(256) void ln_kernel(
    const float* __restrict__ a, const float* __restrict__ bsrc,
    const float* __restrict__ g, const float* __restrict__ beta,
    float* __restrict__ out)
{
    int row  = (blockIdx.x * 256 + threadIdx.x) >> 5;
    int lane = threadIdx.x & 31;
    size_t off = (size_t)row * E_ + lane * 8;

    const float4* ap = (const float4*)(a + off);
    const float4* bp = (const float4*)(bsrc + off);
    float4 a0 = ap[0], a1 = ap[1], b0 = bp[0], b1 = bp[1];
    float v[8];
    v[0] = a0.x + b0.x; v[1] = a0.y + b0.y; v[2] = a0.z + b0.z; v[3] = a0.w + b0.w;
    v[4] = a1.x + b1.x; v[5] = a1.y + b1.y; v[6] = a1.z + b1.z; v[7] = a1.w + b1.w;

    float s = 0.f, ss = 0.f;
    #pragma unroll
    for (int i = 0; i < 8; i++) { s += v[i]; ss = fmaf(v[i], v[i], ss); }
    #pragma unroll
    for (int o = 16; o > 0; o >>= 1) {
        s  += __shfl_xor_sync(0xFFFFFFFFu, s,  o);
        ss += __shfl_xor_sync(0xFFFFFFFFu, ss, o);
    }
    float mu  = s * (1.f / E_);
    float var = ss * (1.f / E_) - mu * mu;
    float rs  = rsqrtf(var + 1e-5f);

    const float4* gp  = (const float4*)(g    + lane * 8);
    const float4* bep = (const float4*)(beta + lane * 8);
    float4 g0 = gp[0], g1v = gp[1], e0 = bep[0], e1 = bep[1];

    float4 w;
    w.x = (v[0]-mu)*rs*g0.x + e0.x; w.y = (v[1]-mu)*rs*g0.y + e0.y;
    w.z = (v[2]-mu)*rs*g0.z + e0.z; w.w = (v[3]-mu)*rs*g0.w + e0.w;
    *(float4*)(out + off) = w;
    w.x = (v[4]-mu)*rs*g1v.x + e1.x; w.y = (v[5]-mu)*rs*g1v.y + e1.y;
    w.z = (v[6]-mu)*rs*g1v.z + e1.z; w.w = (v[7]-mu)*rs*g1v.w + e1.w;
    *(float4*)(out + off + 4) = w;
}

// ---------------- qf = cos(theta_ffn) * cos(h @ w_ip^T + b_ip) --------------
__global__ __launch_bounds__(256) void qf_kernel(
    const float* __restrict__ w_ip, const float* __restrict__ b_ip,
    const float* __restrict__ theta_ffn)
{
    int m    = blockIdx.x;
    int j    = threadIdx.x >> 5;
    int lane = threadIdx.x & 31;
    const float* hr = g_h + (size_t)m * E_;
    const float* wr = w_ip + (size_t)j * E_;
    float s = 0.f;
    #pragma unroll
    for (int e = 0; e < E_; e += 32)
        s = fmaf(hr[e + lane], wr[e + lane], s);
    #pragma unroll
    for (int o = 16; o > 0; o >>= 1)
        s += __shfl_xor_sync(0xFFFFFFFFu, s, o);
    if (lane == 0)
        g_qf[m * NQ_ + j] = __cosf(theta_ffn[j]) * __cosf(s + b_ip[j]);
}

// ---------------- hidden = relu(qf @ w1^T + b1)   (K=8) ---------------------
__global__ __launch_bounds__(256) void hidden_kernel(
    const float* __restrict__ w1, const float* __restrict__ b1)
{
    int m = blockIdx.x >> 2;
    int f = ((blockIdx.x & 3) << 8) + threadIdx.x;
    const float* qr = g_qf + (size_t)m * NQ_;
    const float* wr = w1 + (size_t)f * NQ_;
    float s = b1[f];
    #pragma unroll
    for (int j = 0; j < NQ_; j++)
        s = fmaf(qr[j], wr[j], s);
    g_hidden[(size_t)m * FF_ + f] = fmaxf(s, 0.f);
}

// ---------------- launch ----------------------------------------------------
extern "C" void kernel_launch(void* const* d_in, const int* in_sizes, int n_in,
                              void* d_out, int out_size)
{
    (void)in_sizes; (void)n_in; (void)out_size;

    const float* x          = (const float*)d_in[0];
    const float* theta_attn = (const float*)d_in[1];
    const float* w_in       = (const float*)d_in[2];
    const float* b_in       = (const float*)d_in[3];
    const float* w_out      = (const float*)d_in[4];
    const float* b_out      = (const float*)d_in[5];
    const float* w_comb     = (const float*)d_in[6];
    const float* b_comb     = (const float*)d_in[7];
    const float* g1         = (const float*)d_in[8];
    const float* be1        = (const float*)d_in[9];
    const float* g2         = (const float*)d_in[10];
    const float* be2        = (const float*)d_in[11];
    const float* w_ip       = (const float*)d_in[12];
    const float* b_ip       = (const float*)d_in[13];
    const float* theta_ffn  = (const float*)d_in[14];
    const float* w1         = (const float*)d_in[15];
    const float* b1         = (const float*)d_in[16];
    const float* w2         = (const float*)d_in[17];
    const float* b2         = (const float*)d_in[18];
    float* out = (float*)d_out;

    float *p_qout, *p_qkv, *p_ctx, *p_Wf, *p_bf, *p_tmp, *p_h, *p_hidden;
    cudaGetSymbolAddress((void**)&p_qout,   g_qout);
    cudaGetSymbolAddress((void**)&p_qkv,    g_qkv);
    cudaGetSymbolAddress((void**)&p_ctx,    g_ctx);
    cudaGetSymbolAddress((void**)&p_Wf,     g_Wf);
    cudaGetSymbolAddress((void**)&p_bf,     g_bf);
    cudaGetSymbolAddress((void**)&p_tmp,    g_tmp);
    cudaGetSymbolAddress((void**)&p_h,      g_h);
    cudaGetSymbolAddress((void**)&p_hidden, g_hidden);

    cudaFuncSetAttribute(attn_kernel,
                         cudaFuncAttributeMaxDynamicSharedMemorySize,
                         2 * S_ * DK_ * sizeof(float));

    // 1. q_out = cos(x + theta)
    cos_encode_kernel<<<(M_ * E_) / 1024, 256>>>(x, theta_attn);

    // 2. fold w_comb @ w_out
    fold_w_kernel<<<E_, 256>>>(w_comb, w_out, b_out, b_comb);

    // 3. qkv = q_out @ w_in^T + b_in      [4096 x 768]
    {
        dim3 grid((3 * E_) / 64, M_ / 128);
        sgemm2_kernel<<<grid, 256>>>(p_qout, w_in, b_in, p_qkv,
                                     M_, 3 * E_, E_, 0);
    }

    // 4. attention -> ctx                 [4096 x 256]
    {
        dim3 grid(2, B_ * H_);
        attn_kernel<<<grid, 256, 2 * S_ * DK_ * sizeof(float)>>>();
    }

    // 5. attn_out = ctx @ Wf^T + bf       [4096 x 256]
    {
        dim3 grid(E_ / 64, M_ / 128);
        sgemm2_kernel<<<grid, 256>>>(p_ctx, p_Wf, p_bf, p_tmp,
                                     M_, E_, E_, 0);
    }

    // 6. h = LN(x + attn_out) * g1 + be1
    ln_kernel<<<M_ / 8, 256>>>(x, p_tmp, g1, be1, p_h);

    // 7. qf = cos(theta_ffn) * cos(h @ w_ip^T + b_ip)
    qf_kernel<<<M_, 256>>>(w_ip, b_ip, theta_ffn);

    // 8. hidden = relu(qf @ w1^T + b1)    [4096 x 1024]
    hidden_kernel<<<M_ * 4, 256>>>(w1, b1);

    // 9. ffn_out = hidden @ w2^T + b2     [4096 x 256]
    {
        dim3 grid(E_ / 64, M_ / 128);
        sgemm2_kernel<<<grid, 256>>>(p_hidden, w2, b2, p_tmp,
                                     M_, E_, FF_, 0);
    }

    // 10. out = LN(h + ffn_out) * g2 + be2
    ln_kernel<<<M_ / 8, 256>>>(p_h, p_tmp, g2, be2, out);
}

// round 3
// speedup vs baseline: 1.1383x; 1.0464x over previous
#include <cuda_runtime.h>
#include <math.h>
#include <stdint.h>

// Problem constants
#define B_   4
#define S_   1024
#define E_   256
#define H_   32
#define DK_  8
#define NQ_  8
#define FF_  1024
#define M_   (B_ * S_)   // 4096

typedef unsigned long long ULL;

// ---------------- f32x2 packed math helpers (PTX-only on sm_103a) ----------
__device__ __forceinline__ ULL fma2(ULL a, ULL b, ULL c) {
    ULL d; asm("fma.rn.f32x2 %0, %1, %2, %3;" : "=l"(d) : "l"(a), "l"(b), "l"(c)); return d;
}
__device__ __forceinline__ ULL mul2(ULL a, ULL b) {
    ULL d; asm("mul.rn.f32x2 %0, %1, %2;" : "=l"(d) : "l"(a), "l"(b)); return d;
}
__device__ __forceinline__ ULL pk(float lo, float hi) {
    ULL r; asm("mov.b64 %0, {%1, %2};" : "=l"(r) : "f"(lo), "f"(hi)); return r;
}
__device__ __forceinline__ void unpk(ULL v, float& lo, float& hi) {
    asm("mov.b64 {%0, %1}, %2;" : "=f"(lo), "=f"(hi) : "l"(v));
}
__device__ __forceinline__ float ex2f_(float x) {
    float y; asm("ex2.approx.f32 %0, %1;" : "=f"(y) : "f"(x)); return y;
}

// ---------------- scratch (device globals; no runtime allocation) ----------
__device__ __align__(16) float g_qout[M_ * E_];
__device__ __align__(16) float g_qkv[M_ * 3 * E_];
__device__ __align__(16) float g_ctx[M_ * E_];
__device__ __align__(16) float g_Wf[E_ * E_];
__device__ __align__(16) float g_bf[E_];
__device__ __align__(16) float g_tmp[M_ * E_];
__device__ __align__(16) float g_h[M_ * E_];
__device__ __align__(16) float g_qf[M_ * NQ_];
__device__ __align__(16) float g_hidden[M_ * FF_];
// split-K attention partials: indexed by (bh*4 + kq)*1024 + q
__device__ __align__(16) float2 g_pml[128 * 4 * 1024];      // (m, l)
__device__ __align__(16) ULL    g_pacc[128 * 4 * 1024 * 4]; // acc (4 packed pairs)

// ---------------- q_out = cos(x + theta[e % 8]), float4 --------------------
__global__ __launch_bounds__(256) void cos_encode_kernel(
    const float* __restrict__ x, const float* __restrict__ theta)
{
    int i = (blockIdx.x * 256 + threadIdx.x) * 4;
    float4 v = *(const float4*)(x + i);
    int j = i & 7;
    v.x = __cosf(v.x + theta[j + 0]);
    v.y = __cosf(v.y + theta[j + 1]);
    v.z = __cosf(v.z + theta[j + 2]);
    v.w = __cosf(v.w + theta[j + 3]);
    *(float4*)(g_qout + i) = v;
}

// ---------------- fold: Wf = w_comb @ w_out, bf = w_comb@b_out + b_comb -----
__global__ __launch_bounds__(256) void fold_w_kernel(
    const float* __restrict__ w_comb, const float* __restrict__ w_out,
    const float* __restrict__ b_out, const float* __restrict__ b_comb)
{
    int i = blockIdx.x;
    int j = threadIdx.x;
    float s = 0.f;
    #pragma unroll 8
    for (int k = 0; k < E_; k++)
        s = fmaf(w_comb[i * E_ + k], w_out[k * E_ + j], s);
    g_Wf[i * E_ + j] = s;

    __shared__ float red[256];
    red[j] = w_comb[i * E_ + j] * b_out[j];
    __syncthreads();
    #pragma unroll
    for (int off = 128; off > 0; off >>= 1) {
        if (j < off) red[j] += red[j + off];
        __syncthreads();
    }
    if (j == 0) g_bf[i] = red[0] + b_comb[i];
}

// ---------------- f32x2 SGEMM: C[M,N] = A[M,K] @ Bw[N,K]^T + bias ----------
__global__ __launch_bounds__(256) void sgemm2_kernel(
    const float* __restrict__ A, const float* __restrict__ Bw,
    const float* __restrict__ bias, float* __restrict__ C,
    int M, int N, int K, int relu)
{
    __shared__ float As[16][132];
    __shared__ float Bs[16][68];

    int tid = threadIdx.x;
    int bm = blockIdx.y * 128;
    int bn = blockIdx.x * 64;
    int ty = tid >> 4;
    int tx = tid & 15;

    int alr = tid >> 1;
    int alc = (tid & 1) * 8;
    int blr = tid >> 2;
    int blc = (tid & 3) * 4;

    const float* Aptr = A  + (size_t)(bm + alr) * K + alc;
    const float* Bptr = Bw + (size_t)(bn + blr) * K + blc;

    float4 a0 = *(const float4*)(Aptr);
    float4 a1 = *(const float4*)(Aptr + 4);
    float4 b0 = *(const float4*)(Bptr);

    ULL acc[4][4];
    #pragma unroll
    for (int r = 0; r < 4; r++)
        #pragma unroll
        for (int j = 0; j < 4; j++) acc[r][j] = 0ULL;

    for (int k0 = 0; ; k0 += 16) {
        As[alc + 0][alr] = a0.x; As[alc + 1][alr] = a0.y;
        As[alc + 2][alr] = a0.z; As[alc + 3][alr] = a0.w;
        As[alc + 4][alr] = a1.x; As[alc + 5][alr] = a1.y;
        As[alc + 6][alr] = a1.z; As[alc + 7][alr] = a1.w;
        Bs[blc + 0][blr] = b0.x; Bs[blc + 1][blr] = b0.y;
        Bs[blc + 2][blr] = b0.z; Bs[blc + 3][blr] = b0.w;
        __syncthreads();

        bool last = (k0 + 16 >= K);
        if (!last) {
            Aptr += 16; Bptr += 16;
            a0 = *(const float4*)(Aptr);
            a1 = *(const float4*)(Aptr + 4);
            b0 = *(const float4*)(Bptr);
        }

        #pragma unroll
        for (int kk = 0; kk < 16; kk++) {
            ulonglong2 am0 = *(const ulonglong2*)&As[kk][ty * 8];
            ulonglong2 am1 = *(const ulonglong2*)&As[kk][ty * 8 + 4];
            float4 b4 = *(const float4*)&Bs[kk][tx * 4];
            ULL bb0 = pk(b4.x, b4.x), bb1 = pk(b4.y, b4.y);
            ULL bb2 = pk(b4.z, b4.z), bb3 = pk(b4.w, b4.w);
            ULL am[4] = {am0.x, am0.y, am1.x, am1.y};
            #pragma unroll
            for (int r = 0; r < 4; r++) {
                acc[r][0] = fma2(am[r], bb0, acc[r][0]);
                acc[r][1] = fma2(am[r], bb1, acc[r][1]);
                acc[r][2] = fma2(am[r], bb2, acc[r][2]);
                acc[r][3] = fma2(am[r], bb3, acc[r][3]);
            }
        }
        if (last) break;
        __syncthreads();
    }

    int col = bn + tx * 4;
    float4 bb = *(const float4*)(bias + col);
    #pragma unroll
    for (int r = 0; r < 4; r++) {
        float lo0, hi0, lo1, hi1, lo2v, hi2, lo3, hi3;
        unpk(acc[r][0], lo0, hi0);
        unpk(acc[r][1], lo1, hi1);
        unpk(acc[r][2], lo2v, hi2);
        unpk(acc[r][3], lo3, hi3);
        int row0 = bm + ty * 8 + 2 * r;
        float4 v;
        v.x = lo0 + bb.x; v.y = lo1 + bb.y; v.z = lo2v + bb.z; v.w = lo3 + bb.w;
        if (relu) { v.x = fmaxf(v.x, 0.f); v.y = fmaxf(v.y, 0.f);
                    v.z = fmaxf(v.z, 0.f); v.w = fmaxf(v.w, 0.f); }
        *(float4*)(C + (size_t)row0 * N + col) = v;
        v.x = hi0 + bb.x; v.y = hi1 + bb.y; v.z = hi2 + bb.z; v.w = hi3 + bb.w;
        if (relu) { v.x = fmaxf(v.x, 0.f); v.y = fmaxf(v.y, 0.f);
                    v.z = fmaxf(v.z, 0.f); v.w = fmaxf(v.w, 0.f); }
        *(float4*)(C + (size_t)(row0 + 1) * N + col) = v;
    }
}

// ---------------- attention pass 1: split-K, branchless online softmax ------
// grid = (4 key-quarters, 2 query-halves, 128 bh), 256 threads.
// Each CTA: 512 queries (2/thread) x 256 keys (16 KB smem).
// Scores computed in log2 domain (Q pre-scaled by log2e/sqrt(dk)).
__global__ __launch_bounds__(256) void attn_p1_kernel()
{
    __shared__ float smbuf[256 * 16];     // 16 KB: K[256x8] then V[256x8]
    float* Ks = smbuf;
    float* Vs = smbuf + 256 * DK_;

    int kq = blockIdx.x;
    int qh = blockIdx.y;
    int bh = blockIdx.z;
    int b = bh >> 5;
    int h = bh & 31;
    int tid = threadIdx.x;
    const float* base = g_qkv + (size_t)b * S_ * (3 * E_) + h * DK_;

    // stage: one key per thread
    {
        int sk = kq * 256 + tid;
        const float4* kp = (const float4*)(base + (size_t)sk * (3 * E_) + E_);
        const float4* vp = (const float4*)(base + (size_t)sk * (3 * E_) + 2 * E_);
        float4 k0 = kp[0], k1 = kp[1], v0 = vp[0], v1 = vp[1];
        ((float4*)Ks)[2 * tid]     = k0;
        ((float4*)Ks)[2 * tid + 1] = k1;
        ((float4*)Vs)[2 * tid]     = v0;
        ((float4*)Vs)[2 * tid + 1] = v1;
    }
    __syncthreads();

    const float qscale = 0.35355339059327373f * 1.4426950408889634f;
    int qi0 = qh * 512 + tid;
    int qi1 = qi0 + 256;

    ULL qp0[4], qp1[4];
    {
        const float4* p0 = (const float4*)(base + (size_t)qi0 * (3 * E_));
        const float4* p1 = (const float4*)(base + (size_t)qi1 * (3 * E_));
        float4 t0 = p0[0], t1 = p0[1], u0 = p1[0], u1 = p1[1];
        qp0[0] = pk(t0.x * qscale, t0.y * qscale);
        qp0[1] = pk(t0.z * qscale, t0.w * qscale);
        qp0[2] = pk(t1.x * qscale, t1.y * qscale);
        qp0[3] = pk(t1.z * qscale, t1.w * qscale);
        qp1[0] = pk(u0.x * qscale, u0.y * qscale);
        qp1[1] = pk(u0.z * qscale, u0.w * qscale);
        qp1[2] = pk(u1.x * qscale, u1.y * qscale);
        qp1[3] = pk(u1.z * qscale, u1.w * qscale);
    }

    ULL acc0[4], acc1[4];
    #pragma unroll
    for (int j = 0; j < 4; j++) { acc0[j] = 0ULL; acc1[j] = 0ULL; }
    float m0 = -1e30f, m1 = -1e30f, l0 = 0.f, l1 = 0.f;

    const ulonglong2* K2 = (const ulonglong2*)Ks;
    const ulonglong2* V2 = (const ulonglong2*)Vs;

    for (int s = 0; s < 256; s += 2) {
        ulonglong2 ka0 = K2[2 * s],     kb0 = K2[2 * s + 1];
        ulonglong2 ka1 = K2[2 * s + 2], kb1 = K2[2 * s + 3];

        // 4 independent packed dot chains
        ULL t00 = mul2(qp0[0], ka0.x);
        ULL t01 = mul2(qp0[0], ka1.x);
        ULL t10 = mul2(qp1[0], ka0.x);
        ULL t11 = mul2(qp1[0], ka1.x);
        t00 = fma2(qp0[1], ka0.y, t00);
        t01 = fma2(qp0[1], ka1.y, t01);
        t10 = fma2(qp1[1], ka0.y, t10);
        t11 = fma2(qp1[1], ka1.y, t11);
        t00 = fma2(qp0[2], kb0.x, t00);
        t01 = fma2(qp0[2], kb1.x, t01);
        t10 = fma2(qp1[2], kb0.x, t10);
        t11 = fma2(qp1[2], kb1.x, t11);
        t00 = fma2(qp0[3], kb0.y, t00);
        t01 = fma2(qp0[3], kb1.y, t01);
        t10 = fma2(qp1[3], kb0.y, t10);
        t11 = fma2(qp1[3], kb1.y, t11);

        float d00, d01, d10, d11, x0, x1;
        unpk(t00, x0, x1); d00 = x0 + x1;
        unpk(t01, x0, x1); d01 = x0 + x1;
        unpk(t10, x0, x1); d10 = x0 + x1;
        unpk(t11, x0, x1); d11 = x0 + x1;

        ulonglong2 va0 = V2[2 * s],     vb0 = V2[2 * s + 1];
        ulonglong2 va1 = V2[2 * s + 2], vb1 = V2[2 * s + 3];

        // branchless rescale, amortized over 2 keys
        float nm0 = fmaxf(m0, fmaxf(d00, d01));
        float nm1 = fmaxf(m1, fmaxf(d10, d11));
        float c0  = ex2f_(m0 - nm0);
        float c1  = ex2f_(m1 - nm1);
        float p00 = ex2f_(d00 - nm0);
        float p01 = ex2f_(d01 - nm0);
        float p10 = ex2f_(d10 - nm1);
        float p11 = ex2f_(d11 - nm1);
        m0 = nm0; m1 = nm1;
        l0 = fmaf(l0, c0, p00 + p01);
        l1 = fmaf(l1, c1, p10 + p11);

        ULL cp0 = pk(c0, c0), pb00 = pk(p00, p00), pb01 = pk(p01, p01);
        ULL cp1 = pk(c1, c1), pb10 = pk(p10, p10), pb11 = pk(p11, p11);

        acc0[0] = fma2(pb01, va1.x, fma2(pb00, va0.x, mul2(acc0[0], cp0)));
        acc0[1] = fma2(pb01, va1.y, fma2(pb00, va0.y, mul2(acc0[1], cp0)));
        acc0[2] = fma2(pb01, vb1.x, fma2(pb00, vb0.x, mul2(acc0[2], cp0)));
        acc0[3] = fma2(pb01, vb1.y, fma2(pb00, vb0.y, mul2(acc0[3], cp0)));
        acc1[0] = fma2(pb11, va1.x, fma2(pb10, va0.x, mul2(acc1[0], cp1)));
        acc1[1] = fma2(pb11, va1.y, fma2(pb10, va0.y, mul2(acc1[1], cp1)));
        acc1[2] = fma2(pb11, vb1.x, fma2(pb10, vb0.x, mul2(acc1[2], cp1)));
        acc1[3] = fma2(pb11, vb1.y, fma2(pb10, vb0.y, mul2(acc1[3], cp1)));
    }

    // write partials
    int pbase = (bh * 4 + kq) * 1024;
    g_pml[pbase + qi0] = make_float2(m0, l0);
    g_pml[pbase + qi1] = make_float2(m1, l1);
    {
        ulonglong2* pa = (ulonglong2*)&g_pacc[(size_t)(pbase + qi0) * 4];
        ulonglong2 w;
        w.x = acc0[0]; w.y = acc0[1]; pa[0] = w;
        w.x = acc0[2]; w.y = acc0[3]; pa[1] = w;
        ulonglong2* pb = (ulonglong2*)&g_pacc[(size_t)(pbase + qi1) * 4];
        w.x = acc1[0]; w.y = acc1[1]; pb[0] = w;
        w.x = acc1[2]; w.y = acc1[3]; pb[1] = w;
    }
}

// ---------------- attention pass 2: combine 4 partials per (bh, q) ----------
__global__ __launch_bounds__(256) void attn_p2_kernel()
{
    int idx = blockIdx.x * 256 + threadIdx.x;   // 131072
    int bh = idx >> 10;
    int q  = idx & 1023;
    int b = bh >> 5;
    int h = bh & 31;
    int base = bh * 4 * 1024 + q;

    float2 ml0 = g_pml[base];
    float2 ml1 = g_pml[base + 1024];
    float2 ml2 = g_pml[base + 2048];
    float2 ml3 = g_pml[base + 3072];
    float M = fmaxf(fmaxf(ml0.x, ml1.x), fmaxf(ml2.x, ml3.x));
    float w0 = ex2f_(ml0.x - M);
    float w1 = ex2f_(ml1.x - M);
    float w2 = ex2f_(ml2.x - M);
    float w3 = ex2f_(ml3.x - M);
    float L = ml0.y * w0 + ml1.y * w1 + ml2.y * w2 + ml3.y * w3;
    float r = 1.f / L;
    w0 *= r; w1 *= r; w2 *= r; w3 *= r;
    ULL wp[4] = {pk(w0, w0), pk(w1, w1), pk(w2, w2), pk(w3, w3)};

    ULL c[4] = {0ULL, 0ULL, 0ULL, 0ULL};
    #pragma unroll
    for (int k = 0; k < 4; k++) {
        const ulonglong2* pa = (const ulonglong2*)&g_pacc[(size_t)(base + k * 1024) * 4];
        ulonglong2 a0 = pa[0], a1 = pa[1];
        c[0] = fma2(wp[k], a0.x, c[0]);
        c[1] = fma2(wp[k], a0.y, c[1]);
        c[2] = fma2(wp[k], a1.x, c[2]);
        c[3] = fma2(wp[k], a1.y, c[3]);
    }

    ulonglong2* op = (ulonglong2*)(g_ctx + ((size_t)b * S_ + q) * E_ + h * DK_);
    ulonglong2 w;
    w.x = c[0]; w.y = c[1]; op[0] = w;
    w.x = c[2]; w.y = c[3]; op[1] = w;
}

// ---------------- layernorm: out = LN(a + b) * g + beta  (warp per row) -----
__global__ __launch_bounds__(256) void ln_kernel(
    const float* __restrict__ a, const float* __restrict__ bsrc,
    const float* __restrict__ g, const float* __restrict__ beta,
    float* __restrict__ out)
{
    int row  = (blockIdx.x * 256 + threadIdx.x) >> 5;
    int lane = threadIdx.x & 31;
    size_t off = (size_t)row * E_ + lane * 8;

    const float4* ap = (const float4*)(a + off);
    const float4* bp = (const float4*)(bsrc + off);
    float4 a0 = ap[0], a1 = ap[1], b0 = bp[0], b1 = bp[1];
    float v[8];
    v[0] = a0.x + b0.x; v[1] = a0.y + b0.y; v[2] = a0.z + b0.z; v[3] = a0.w + b0.w;
    v[4] = a1.x + b1.x; v[5] = a1.y + b1.y; v[6] = a1.z + b1.z; v[7] = a1.w + b1.w;

    float s = 0.f, ss = 0.f;
    #pragma unroll
    for (int i = 0; i < 8; i++) { s += v[i]; ss = fmaf(v[i], v[i], ss); }
    #pragma unroll
    for (int o = 16; o > 0; o >>= 1) {
        s  += __shfl_xor_sync(0xFFFFFFFFu, s,  o);
        ss += __shfl_xor_sync(0xFFFFFFFFu, ss, o);
    }
    float mu  = s * (1.f / E_);
    float var = ss * (1.f / E_) - mu * mu;
    float rs  = rsqrtf(var + 1e-5f);

    const float4* gp  = (const float4*)(g    + lane * 8);
    const float4* bep = (const float4*)(beta + lane * 8);
    float4 g0 = gp[0], g1v = gp[1], e0 = bep[0], e1 = bep[1];

    float4 w;
    w.x = (v[0]-mu)*rs*g0.x + e0.x; w.y = (v[1]-mu)*rs*g0.y + e0.y;
    w.z = (v[2]-mu)*rs*g0.z + e0.z; w.w = (v[3]-mu)*rs*g0.w + e0.w;
    *(float4*)(out + off) = w;
    w.x = (v[4]-mu)*rs*g1v.x + e1.x; w.y = (v[5]-mu)*rs*g1v.y + e1.y;
    w.z = (v[6]-mu)*rs*g1v.z + e1.z; w.w = (v[7]-mu)*rs*g1v.w + e1.w;
    *(float4*)(out + off + 4) = w;
}

// ---------------- qf = cos(theta_ffn) * cos(h @ w_ip^T + b_ip) --------------
__global__ __launch_bounds__(256) void qf_kernel(
    const float* __restrict__ w_ip, const float* __restrict__ b_ip,
    const float* __restrict__ theta_ffn)
{
    int m    = blockIdx.x;
    int j    = threadIdx.x >> 5;
    int lane = threadIdx.x & 31;
    const float* hr = g_h + (size_t)m * E_;
    const float* wr = w_ip + (size_t)j * E_;
    float s = 0.f;
    #pragma unroll
    for (int e = 0; e < E_; e += 32)
        s = fmaf(hr[e + lane], wr[e + lane], s);
    #pragma unroll
    for (int o = 16; o > 0; o >>= 1)
        s += __shfl_xor_sync(0xFFFFFFFFu, s, o);
    if (lane == 0)
        g_qf[m * NQ_ + j] = __cosf(theta_ffn[j]) * __cosf(s + b_ip[j]);
}

// ---------------- hidden = relu(qf @ w1^T + b1)   (K=8) ---------------------
__global__ __launch_bounds__(256) void hidden_kernel(
    const float* __restrict__ w1, const float* __restrict__ b1)
{
    int m = blockIdx.x >> 2;
    int f = ((blockIdx.x & 3) << 8) + threadIdx.x;
    const float* qr = g_qf + (size_t)m * NQ_;
    const float* wr = w1 + (size_t)f * NQ_;
    float s = b1[f];
    #pragma unroll
    for (int j = 0; j < NQ_; j++)
        s = fmaf(qr[j], wr[j], s);
    g_hidden[(size_t)m * FF_ + f] = fmaxf(s, 0.f);
}

// ---------------- launch ----------------------------------------------------
extern "C" void kernel_launch(void* const* d_in, const int* in_sizes, int n_in,
                              void* d_out, int out_size)
{
    (void)in_sizes; (void)n_in; (void)out_size;

    const float* x          = (const float*)d_in[0];
    const float* theta_attn = (const float*)d_in[1];
    const float* w_in       = (const float*)d_in[2];
    const float* b_in       = (const float*)d_in[3];
    const float* w_out      = (const float*)d_in[4];
    const float* b_out      = (const float*)d_in[5];
    const float* w_comb     = (const float*)d_in[6];
    const float* b_comb     = (const float*)d_in[7];
    const float* g1         = (const float*)d_in[8];
    const float* be1        = (const float*)d_in[9];
    const float* g2         = (const float*)d_in[10];
    const float* be2        = (const float*)d_in[11];
    const float* w_ip       = (const float*)d_in[12];
    const float* b_ip       = (const float*)d_in[13];
    const float* theta_ffn  = (const float*)d_in[14];
    const float* w1         = (const float*)d_in[15];
    const float* b1         = (const float*)d_in[16];
    const float* w2         = (const float*)d_in[17];
    const float* b2         = (const float*)d_in[18];
    float* out = (float*)d_out;

    float *p_qout, *p_qkv, *p_ctx, *p_Wf, *p_bf, *p_tmp, *p_h, *p_hidden;
    cudaGetSymbolAddress((void**)&p_qout,   g_qout);
    cudaGetSymbolAddress((void**)&p_qkv,    g_qkv);
    cudaGetSymbolAddress((void**)&p_ctx,    g_ctx);
    cudaGetSymbolAddress((void**)&p_Wf,     g_Wf);
    cudaGetSymbolAddress((void**)&p_bf,     g_bf);
    cudaGetSymbolAddress((void**)&p_tmp,    g_tmp);
    cudaGetSymbolAddress((void**)&p_h,      g_h);
    cudaGetSymbolAddress((void**)&p_hidden, g_hidden);

    // 1. q_out = cos(x + theta)
    cos_encode_kernel<<<(M_ * E_) / 1024, 256>>>(x, theta_attn);

    // 2. fold w_comb @ w_out
    fold_w_kernel<<<E_, 256>>>(w_comb, w_out, b_out, b_comb);

    // 3. qkv = q_out @ w_in^T + b_in      [4096 x 768]
    {
        dim3 grid((3 * E_) / 64, M_ / 128);
        sgemm2_kernel<<<grid, 256>>>(p_qout, w_in, b_in, p_qkv,
                                     M_, 3 * E_, E_, 0);
    }

    // 4a. attention pass 1 (split-K partials)
    {
        dim3 grid(4, 2, B_ * H_);
        attn_p1_kernel<<<grid, 256>>>();
    }
    // 4b. attention pass 2 (combine) -> ctx
    attn_p2_kernel<<<(B_ * H_ * S_) / 256, 256>>>();

    // 5. attn_out = ctx @ Wf^T + bf       [4096 x 256]
    {
        dim3 grid(E_ / 64, M_ / 128);
        sgemm2_kernel<<<grid, 256>>>(p_ctx, p_Wf, p_bf, p_tmp,
                                     M_, E_, E_, 0);
    }

    // 6. h = LN(x + attn_out) * g1 + be1
    ln_kernel<<<M_ / 8, 256>>>(x, p_tmp, g1, be1, p_h);

    // 7. qf = cos(theta_ffn) * cos(h @ w_ip^T + b_ip)
    qf_kernel<<<M_, 256>>>(w_ip, b_ip, theta_ffn);

    // 8. hidden = relu(qf @ w1^T + b1)    [4096 x 1024]
    hidden_kernel<<<M_ * 4, 256>>>(w1, b1);

    // 9. ffn_out = hidden @ w2^T + b2     [4096 x 256]
    {
        dim3 grid(E_ / 64, M_ / 128);
        sgemm2_kernel<<<grid, 256>>>(p_hidden, w2, b2, p_tmp,
                                     M_, E_, FF_, 0);
    }

    // 10. out = LN(h + ffn_out) * g2 + be2
    ln_kernel<<<M_ / 8, 256>>>(p_h, p_tmp, g2, be2, out);
}